// round 8
// baseline (speedup 1.0000x reference)
#include <cuda_runtime.h>

#define NODES 100000
#define NEDGE 1600000

__device__ unsigned g_deg [NODES];
__device__ float    g_dinv[NODES];
__device__ float4   g_xs  [NODES];
__device__ float4   g_acc1[NODES];
__device__ float4   g_gs  [NODES];
__device__ float4   g_acc2[NODES];

typedef unsigned long long ull;

__device__ __forceinline__ void red_add_v4(float4* addr, float4 v) {
    asm volatile("red.global.add.v4.f32 [%0], {%1,%2,%3,%4};"
                 :: "l"(addr), "f"(v.x), "f"(v.y), "f"(v.z), "f"(v.w)
                 : "memory");
}

__device__ __forceinline__ void red_add_u32(unsigned* addr) {
    asm volatile("red.global.add.u32 [%0], 1;" :: "l"(addr) : "memory");
}

__device__ __forceinline__ ull pk2(float lo, float hi) {
    ull r; asm("mov.b64 %0, {%1, %2};" : "=l"(r) : "f"(lo), "f"(hi)); return r;
}
__device__ __forceinline__ void upk2(float& lo, float& hi, ull v) {
    asm("mov.b64 {%0, %1}, %2;" : "=f"(lo), "=f"(hi) : "l"(v));
}
__device__ __forceinline__ ull fma2(ull a, ull b, ull c) {
    ull d; asm("fma.rn.f32x2 %0, %1, %2, %3;" : "=l"(d) : "l"(a), "l"(b), "l"(c)); return d;
}

// deg[col[e]] += 1, 2 edges/thread
__global__ void __launch_bounds__(256) k_deg_count(const int* __restrict__ col, int e) {
    int t = blockIdx.x * blockDim.x + threadIdx.x;
    int base = t * 2;
    if (base + 1 < e) {
        int2 c = ((const int2*)col)[t];
        red_add_u32(&g_deg[c.x]);
        red_add_u32(&g_deg[c.y]);
    } else if (base < e) {
        red_add_u32(&g_deg[col[base]]);
    }
}

// dinv = rsqrt(deg + 1 self-loop); xs = x * dinv; acc1 init = xs (self loop)
__global__ void k_node_pre(const float4* __restrict__ x, int n) {
    int i = blockIdx.x * blockDim.x + threadIdx.x;
    if (i < n) {
        float d = rsqrtf((float)(g_deg[i] + 1u));
        g_dinv[i] = d;
        float4 v = x[i];
        v.x *= d; v.y *= d; v.z *= d; v.w *= d;
        g_xs[i]   = v;
        g_acc1[i] = v;
    }
}

// 2-edge scatter: dst[col[e]] += src[row[e]]
__global__ void __launch_bounds__(256) k_scatter(const int* __restrict__ row,
                                                 const int* __restrict__ col,
                                                 const float4* __restrict__ src,
                                                 float4* __restrict__ dst, int e) {
    int t = blockIdx.x * blockDim.x + threadIdx.x;
    int base = t * 2;
    if (base + 1 < e) {
        int2 r = ((const int2*)row)[t];
        int2 c = ((const int2*)col)[t];
        float4 v0 = src[r.x];
        float4 v1 = src[r.y];
        red_add_v4(&dst[c.x], v0);
        red_add_v4(&dst[c.y], v1);
    } else if (base < e) {
        red_add_v4(&dst[col[base]], src[row[base]]);
    }
}

// Fused per-node MLP using packed f32x2 FMA over j-pairs.
// Smem layout per jp (10 ull = 80B, 16B-aligned stride):
//   [0]=pwx {W1[0][2jp],W1[0][2jp+1]}  [1]=pwy  [2]=pwz  [3]=pww
//   [4]=pu0 {W2[2jp][0],W2[2jp+1][0]}  [5]=pu1  [6]=pu2  [7]=pu3
//   [8]=pb  {b1[2jp],b1[2jp+1]}        [9]=pad
__global__ void __launch_bounds__(64) k_mlp(const float* __restrict__ W1,
                                            const float* __restrict__ b1,
                                            const float* __restrict__ W2, int n) {
    __shared__ ull sbuf[320];  // 32 jp * 10 ull
    int tid = threadIdx.x;
    if (tid < 32) {
        int jp = tid;
        int j = jp * 2;
        float* fs = (float*)(sbuf + jp * 10);
        fs[0] = W1[j];        fs[1] = W1[j + 1];          // wx pair
        fs[2] = W1[64 + j];   fs[3] = W1[64 + j + 1];     // wy
        fs[4] = W1[128 + j];  fs[5] = W1[128 + j + 1];    // wz
        fs[6] = W1[192 + j];  fs[7] = W1[192 + j + 1];    // ww
        fs[8]  = W2[j * 4 + 0]; fs[9]  = W2[j * 4 + 4];   // u0 pair
        fs[10] = W2[j * 4 + 1]; fs[11] = W2[j * 4 + 5];   // u1
        fs[12] = W2[j * 4 + 2]; fs[13] = W2[j * 4 + 6];   // u2
        fs[14] = W2[j * 4 + 3]; fs[15] = W2[j * 4 + 7];   // u3
        fs[16] = b1[j]; fs[17] = b1[j + 1];
    }
    __syncthreads();

    int i0 = (blockIdx.x * blockDim.x + tid) * 2;
    if (i0 + 1 < n) {
        float d0 = g_dinv[i0],  d1 = g_dinv[i0 + 1];
        float4 a0 = g_acc1[i0], a1 = g_acc1[i0 + 1];
        a0.x *= d0; a0.y *= d0; a0.z *= d0; a0.w *= d0;
        a1.x *= d1; a1.y *= d1; a1.z *= d1; a1.w *= d1;
        ull pax0 = pk2(a0.x, a0.x), pay0 = pk2(a0.y, a0.y);
        ull paz0 = pk2(a0.z, a0.z), paw0 = pk2(a0.w, a0.w);
        ull pax1 = pk2(a1.x, a1.x), pay1 = pk2(a1.y, a1.y);
        ull paz1 = pk2(a1.z, a1.z), paw1 = pk2(a1.w, a1.w);
        ull pg00 = 0, pg01 = 0, pg02 = 0, pg03 = 0;  // 0ull == {0.f,0.f}
        ull pg10 = 0, pg11 = 0, pg12 = 0, pg13 = 0;
        #pragma unroll 8
        for (int jp = 0; jp < 32; jp++) {
            const ulonglong2* blk = (const ulonglong2*)(sbuf + jp * 10);
            ulonglong2 w01 = blk[0];   // pwx, pwy
            ulonglong2 w23 = blk[1];   // pwz, pww
            ulonglong2 u01 = blk[2];   // pu0, pu1
            ulonglong2 u23 = blk[3];   // pu2, pu3
            ull pb = sbuf[jp * 10 + 8];

            ull ph0 = fma2(pax0, w01.x, pb);
            ph0 = fma2(pay0, w01.y, ph0);
            ph0 = fma2(paz0, w23.x, ph0);
            ph0 = fma2(paw0, w23.y, ph0);
            float h0a, h0b; upk2(h0a, h0b, ph0);
            h0a = fmaxf(h0a, 0.0f); h0b = fmaxf(h0b, 0.0f);
            ph0 = pk2(h0a, h0b);
            pg00 = fma2(ph0, u01.x, pg00);
            pg01 = fma2(ph0, u01.y, pg01);
            pg02 = fma2(ph0, u23.x, pg02);
            pg03 = fma2(ph0, u23.y, pg03);

            ull ph1 = fma2(pax1, w01.x, pb);
            ph1 = fma2(pay1, w01.y, ph1);
            ph1 = fma2(paz1, w23.x, ph1);
            ph1 = fma2(paw1, w23.y, ph1);
            float h1a, h1b; upk2(h1a, h1b, ph1);
            h1a = fmaxf(h1a, 0.0f); h1b = fmaxf(h1b, 0.0f);
            ph1 = pk2(h1a, h1b);
            pg10 = fma2(ph1, u01.x, pg10);
            pg11 = fma2(ph1, u01.y, pg11);
            pg12 = fma2(ph1, u23.x, pg12);
            pg13 = fma2(ph1, u23.y, pg13);
        }
        float lo, hi;
        float4 s0, s1;
        upk2(lo, hi, pg00); s0.x = (lo + hi) * d0;
        upk2(lo, hi, pg01); s0.y = (lo + hi) * d0;
        upk2(lo, hi, pg02); s0.z = (lo + hi) * d0;
        upk2(lo, hi, pg03); s0.w = (lo + hi) * d0;
        upk2(lo, hi, pg10); s1.x = (lo + hi) * d1;
        upk2(lo, hi, pg11); s1.y = (lo + hi) * d1;
        upk2(lo, hi, pg12); s1.z = (lo + hi) * d1;
        upk2(lo, hi, pg13); s1.w = (lo + hi) * d1;
        g_gs[i0]     = s0;  g_acc2[i0]     = s0;
        g_gs[i0 + 1] = s1;  g_acc2[i0 + 1] = s1;
    } else if (i0 < n) {
        // scalar tail (odd n) reading the packed layout
        float d = g_dinv[i0];
        float4 a = g_acc1[i0];
        a.x *= d; a.y *= d; a.z *= d; a.w *= d;
        float g0 = 0.f, g1 = 0.f, g2 = 0.f, g3 = 0.f;
        for (int jp = 0; jp < 32; jp++) {
            const float* fs = (const float*)(sbuf + jp * 10);
            #pragma unroll
            for (int s = 0; s < 2; s++) {
                float h = fs[16 + s];
                h = fmaf(a.x, fs[0 + s], h);
                h = fmaf(a.y, fs[2 + s], h);
                h = fmaf(a.z, fs[4 + s], h);
                h = fmaf(a.w, fs[6 + s], h);
                h = fmaxf(h, 0.0f);
                g0 = fmaf(h, fs[8 + s],  g0);
                g1 = fmaf(h, fs[10 + s], g1);
                g2 = fmaf(h, fs[12 + s], g2);
                g3 = fmaf(h, fs[14 + s], g3);
            }
        }
        float4 s = make_float4(g0 * d, g1 * d, g2 * d, g3 * d);
        g_gs[i0] = s;  g_acc2[i0] = s;
    }
}

// out = dinv * acc2 + b2
__global__ void k_final(const float* __restrict__ b2, float4* __restrict__ out, int n) {
    int i = blockIdx.x * blockDim.x + threadIdx.x;
    if (i < n) {
        float d = g_dinv[i];
        float4 a = g_acc2[i];
        float4 o;
        o.x = fmaf(d, a.x, b2[0]);
        o.y = fmaf(d, a.y, b2[1]);
        o.z = fmaf(d, a.z, b2[2]);
        o.w = fmaf(d, a.w, b2[3]);
        out[i] = o;
    }
}

extern "C" void kernel_launch(void* const* d_in, const int* in_sizes, int n_in,
                              void* d_out, int out_size) {
    const float* x  = (const float*)d_in[0];
    const int*   ei = (const int*)  d_in[1];
    const float* W1 = (const float*)d_in[2];
    const float* b1 = (const float*)d_in[3];
    const float* W2 = (const float*)d_in[4];
    const float* b2 = (const float*)d_in[5];

    int n = in_sizes[0] / 4;   // N nodes (S=4)
    int e = in_sizes[1] / 2;   // E edges
    const int* row = ei;
    const int* col = ei + e;

    void *p_deg, *p_xs, *p_acc1, *p_gs, *p_acc2;
    cudaGetSymbolAddress(&p_deg,  g_deg);
    cudaGetSymbolAddress(&p_xs,   g_xs);
    cudaGetSymbolAddress(&p_acc1, g_acc1);
    cudaGetSymbolAddress(&p_gs,   g_gs);
    cudaGetSymbolAddress(&p_acc2, g_acc2);

    const int TB  = 256;
    const int TBM = 64;                          // mlp: 2-warp blocks, balanced waves
    int nb_n   = (n + TB - 1) / TB;
    int nt_e2  = (e + 1) / 2;                    // 2 edges/thread
    int nb_e2  = (nt_e2 + TB - 1) / TB;
    int nt_m   = (n + 1) / 2;                    // 2 nodes/thread (mlp)
    int nb_m   = (nt_m + TBM - 1) / TBM;         // 782 blocks

    cudaMemsetAsync(p_deg, 0, n * sizeof(unsigned));
    k_deg_count<<<nb_e2, TB>>>(col, e);
    k_node_pre <<<nb_n,  TB>>>((const float4*)x, n);
    k_scatter  <<<nb_e2, TB>>>(row, col, (const float4*)p_xs, (float4*)p_acc1, e);
    k_mlp      <<<nb_m,  TBM>>>(W1, b1, W2, n);
    k_scatter  <<<nb_e2, TB>>>(row, col, (const float4*)p_gs, (float4*)p_acc2, e);
    k_final    <<<nb_n,  TB>>>(b2, (float4*)d_out, n);
}

// round 9
// speedup vs baseline: 1.4365x; 1.4365x over previous
#include <cuda_runtime.h>

#define NODES 100000
#define NEDGE 1600000

__device__ unsigned g_deg [NODES];
__device__ float    g_dinv[NODES];
__device__ float4   g_xs  [NODES];   // dinv-scaled input features (layer-1 messages)
__device__ float4   g_acc1[NODES];   // layer-1 aggregation accumulator
__device__ float4   g_gs  [NODES];   // dinv-scaled layer-2 messages (after fused MLP)
__device__ float4   g_acc2[NODES];   // layer-2 aggregation accumulator

__device__ __forceinline__ void red_add_v4(float4* addr, float4 v) {
    asm volatile("red.global.add.v4.f32 [%0], {%1,%2,%3,%4};"
                 :: "l"(addr), "f"(v.x), "f"(v.y), "f"(v.z), "f"(v.w)
                 : "memory");
}

__device__ __forceinline__ void red_add_u32(unsigned* addr) {
    asm volatile("red.global.add.u32 [%0], 1;" :: "l"(addr) : "memory");
}

// deg[col[e]] += 1, 1 edge/thread (max occupancy, max outstanding ops)
__global__ void __launch_bounds__(256) k_deg_count(const int* __restrict__ col, int e) {
    int t = blockIdx.x * blockDim.x + threadIdx.x;
    if (t < e) red_add_u32(&g_deg[col[t]]);
}

// dinv = rsqrt(deg + 1 self-loop); xs = x * dinv; acc1 init = xs (self loop);
// deg cleared for the next graph replay (same-thread read-then-zero).
__global__ void k_node_pre(const float4* __restrict__ x, int n) {
    int i = blockIdx.x * blockDim.x + threadIdx.x;
    if (i < n) {
        float d = rsqrtf((float)(g_deg[i] + 1u));
        g_deg[i] = 0u;
        g_dinv[i] = d;
        float4 v = x[i];
        v.x *= d; v.y *= d; v.z *= d; v.w *= d;
        g_xs[i]   = v;
        g_acc1[i] = v;
    }
}

// 1-edge scatter: dst[col[e]] += src[row[e]]; minimal regs -> max occupancy,
// maximizing outstanding L1tex wavefronts (the binding resource).
__global__ void __launch_bounds__(256) k_scatter(const int* __restrict__ row,
                                                 const int* __restrict__ col,
                                                 const float4* __restrict__ src,
                                                 float4* __restrict__ dst, int e) {
    int t = blockIdx.x * blockDim.x + threadIdx.x;
    if (t < e) {
        int r = __ldg(row + t);
        int c = __ldg(col + t);
        red_add_v4(&dst[c], src[r]);
    }
}

// Fused per-node MLP: 2 nodes/thread (ILP to cover LDS latency) AND a
// wave-balanced grid (TB=64 -> 782 blocks of 2 warps, ~10.5 warps/SM).
__global__ void __launch_bounds__(64) k_mlp(const float* __restrict__ W1,
                                            const float* __restrict__ b1,
                                            const float* __restrict__ W2, int n) {
    __shared__ float sW1T[256];  // [j][i] : sW1T[j*4+i] = W1[i*64+j]
    __shared__ float sW2 [256];  // [j][c] row-major (native layout of W2)
    __shared__ float sB1 [64];
    int tid = threadIdx.x;
    #pragma unroll
    for (int k = tid; k < 256; k += 64) {
        sW1T[(k & 63) * 4 + (k >> 6)] = W1[k];  // transpose on load
        sW2[k] = W2[k];
    }
    sB1[tid] = b1[tid];
    __syncthreads();

    const float4* w1t = (const float4*)sW1T;
    const float4* w2  = (const float4*)sW2;

    int i0 = (blockIdx.x * blockDim.x + tid) * 2;
    if (i0 + 1 < n) {
        float d0 = g_dinv[i0],  d1 = g_dinv[i0 + 1];
        float4 a0 = g_acc1[i0], a1 = g_acc1[i0 + 1];
        a0.x *= d0; a0.y *= d0; a0.z *= d0; a0.w *= d0;
        a1.x *= d1; a1.y *= d1; a1.z *= d1; a1.w *= d1;
        float4 g0 = make_float4(0.f, 0.f, 0.f, 0.f);
        float4 g1 = make_float4(0.f, 0.f, 0.f, 0.f);
        #pragma unroll
        for (int j = 0; j < 64; j++) {
            float4 w = w1t[j];
            float4 u = w2[j];
            float  b = sB1[j];
            float h0 = fmaf(a0.x, w.x, fmaf(a0.y, w.y, fmaf(a0.z, w.z, fmaf(a0.w, w.w, b))));
            float h1 = fmaf(a1.x, w.x, fmaf(a1.y, w.y, fmaf(a1.z, w.z, fmaf(a1.w, w.w, b))));
            h0 = fmaxf(h0, 0.0f);
            h1 = fmaxf(h1, 0.0f);
            g0.x = fmaf(h0, u.x, g0.x); g0.y = fmaf(h0, u.y, g0.y);
            g0.z = fmaf(h0, u.z, g0.z); g0.w = fmaf(h0, u.w, g0.w);
            g1.x = fmaf(h1, u.x, g1.x); g1.y = fmaf(h1, u.y, g1.y);
            g1.z = fmaf(h1, u.z, g1.z); g1.w = fmaf(h1, u.w, g1.w);
        }
        float4 s0 = make_float4(g0.x * d0, g0.y * d0, g0.z * d0, g0.w * d0);
        float4 s1 = make_float4(g1.x * d1, g1.y * d1, g1.z * d1, g1.w * d1);
        g_gs[i0]     = s0;  g_acc2[i0]     = s0;
        g_gs[i0 + 1] = s1;  g_acc2[i0 + 1] = s1;
    } else if (i0 < n) {
        float d = g_dinv[i0];
        float4 a = g_acc1[i0];
        a.x *= d; a.y *= d; a.z *= d; a.w *= d;
        float4 g = make_float4(0.f, 0.f, 0.f, 0.f);
        #pragma unroll
        for (int j = 0; j < 64; j++) {
            float4 w = w1t[j];
            float4 u = w2[j];
            float h = fmaf(a.x, w.x, fmaf(a.y, w.y, fmaf(a.z, w.z, fmaf(a.w, w.w, sB1[j]))));
            h = fmaxf(h, 0.0f);
            g.x = fmaf(h, u.x, g.x); g.y = fmaf(h, u.y, g.y);
            g.z = fmaf(h, u.z, g.z); g.w = fmaf(h, u.w, g.w);
        }
        float4 s = make_float4(g.x * d, g.y * d, g.z * d, g.w * d);
        g_gs[i0] = s;  g_acc2[i0] = s;
    }
}

// out = dinv * acc2 + b2
__global__ void k_final(const float* __restrict__ b2, float4* __restrict__ out, int n) {
    int i = blockIdx.x * blockDim.x + threadIdx.x;
    if (i < n) {
        float d = g_dinv[i];
        float4 a = g_acc2[i];
        float4 o;
        o.x = fmaf(d, a.x, b2[0]);
        o.y = fmaf(d, a.y, b2[1]);
        o.z = fmaf(d, a.z, b2[2]);
        o.w = fmaf(d, a.w, b2[3]);
        out[i] = o;
    }
}

extern "C" void kernel_launch(void* const* d_in, const int* in_sizes, int n_in,
                              void* d_out, int out_size) {
    const float* x  = (const float*)d_in[0];
    const int*   ei = (const int*)  d_in[1];
    const float* W1 = (const float*)d_in[2];
    const float* b1 = (const float*)d_in[3];
    const float* W2 = (const float*)d_in[4];
    const float* b2 = (const float*)d_in[5];

    int n = in_sizes[0] / 4;   // N nodes (S=4)
    int e = in_sizes[1] / 2;   // E edges
    const int* row = ei;
    const int* col = ei + e;

    void *p_xs, *p_acc1, *p_gs, *p_acc2;
    cudaGetSymbolAddress(&p_xs,   g_xs);
    cudaGetSymbolAddress(&p_acc1, g_acc1);
    cudaGetSymbolAddress(&p_gs,   g_gs);
    cudaGetSymbolAddress(&p_acc2, g_acc2);

    const int TB  = 256;
    const int TBM = 64;                          // mlp: 2-warp blocks, balanced waves
    int nb_n  = (n + TB - 1) / TB;
    int nb_e1 = (e + TB - 1) / TB;               // 1 edge/thread
    int nt_m  = (n + 1) / 2;                     // 2 nodes/thread (mlp)
    int nb_m  = (nt_m + TBM - 1) / TBM;          // 782 blocks

    k_deg_count<<<nb_e1, TB>>>(col, e);
    k_node_pre <<<nb_n,  TB>>>((const float4*)x, n);
    k_scatter  <<<nb_e1, TB>>>(row, col, (const float4*)p_xs, (float4*)p_acc1, e);
    k_mlp      <<<nb_m,  TBM>>>(W1, b1, W2, n);
    k_scatter  <<<nb_e1, TB>>>(row, col, (const float4*)p_gs, (float4*)p_acc2, e);
    k_final    <<<nb_n,  TB>>>(b2, (float4*)d_out, n);
}

// round 10
// speedup vs baseline: 1.5602x; 1.0861x over previous
#include <cuda_runtime.h>

#define NODES 100000
#define NEDGE 1600000

__device__ unsigned g_deg [NODES];
__device__ float    g_dinv[NODES];
__device__ float4   g_xs  [NODES];   // dinv-scaled input features (layer-1 messages)
__device__ float4   g_acc1[NODES];   // layer-1 aggregation accumulator
__device__ float4   g_gs  [NODES];   // dinv-scaled layer-2 messages (after fused MLP)
__device__ float4   g_acc2[NODES];   // layer-2 aggregation accumulator

__device__ __forceinline__ void red_add_v4(float4* addr, float4 v) {
    asm volatile("red.global.add.v4.f32 [%0], {%1,%2,%3,%4};"
                 :: "l"(addr), "f"(v.x), "f"(v.y), "f"(v.z), "f"(v.w)
                 : "memory");
}

__device__ __forceinline__ void red_add_u32(unsigned* addr) {
    asm volatile("red.global.add.u32 [%0], 1;" :: "l"(addr) : "memory");
}

// deg[col[e]] += 1, 1 edge/thread. No GDS: g_deg's last writer (node_pre of the
// previous replay) is >=4 fully-retired launches back; only final_k can overlap
// us and it shares no data.
__global__ void __launch_bounds__(256) k_deg_count(const int* __restrict__ col, int e) {
    int t = blockIdx.x * blockDim.x + threadIdx.x;
    if (t < e) red_add_u32(&g_deg[col[t]]);
    cudaTriggerProgrammaticLaunchCompletion();
}

// dinv = rsqrt(deg + 1 self-loop); xs = x * dinv; acc1 init = xs (self loop);
// deg cleared for the next replay (same-thread read-then-zero).
__global__ void k_node_pre(const float4* __restrict__ x, int n) {
    int i = blockIdx.x * blockDim.x + threadIdx.x;
    float4 v = make_float4(0.f, 0.f, 0.f, 0.f);
    if (i < n) v = x[i];                 // independent prologue load
    cudaGridDependencySynchronize();     // wait: all deg_count reds landed
    if (i < n) {
        float d = rsqrtf((float)(g_deg[i] + 1u));
        g_deg[i] = 0u;
        g_dinv[i] = d;
        v.x *= d; v.y *= d; v.z *= d; v.w *= d;
        g_xs[i]   = v;
        g_acc1[i] = v;
    }
    cudaTriggerProgrammaticLaunchCompletion();
}

// 1-edge scatter: dst[col[e]] += src[row[e]]. Index loads are independent of
// the predecessor; gather+red happen after GDS.
__global__ void __launch_bounds__(256) k_scatter(const int* __restrict__ row,
                                                 const int* __restrict__ col,
                                                 const float4* __restrict__ src,
                                                 float4* __restrict__ dst, int e) {
    int t = blockIdx.x * blockDim.x + threadIdx.x;
    int r = 0, c = 0;
    bool ok = t < e;
    if (ok) { r = __ldg(row + t); c = __ldg(col + t); }  // independent prologue
    cudaGridDependencySynchronize();     // wait: src fully written
    if (ok) red_add_v4(&dst[c], src[r]);
    cudaTriggerProgrammaticLaunchCompletion();
}

// Fused per-node MLP: 2 nodes/thread, TB=64 (782 balanced 2-warp blocks).
// Weight staging to smem is independent of scatter1; GDS before reading acc1.
__global__ void __launch_bounds__(64) k_mlp(const float* __restrict__ W1,
                                            const float* __restrict__ b1,
                                            const float* __restrict__ W2, int n) {
    __shared__ float sW1T[256];  // [j][i] : sW1T[j*4+i] = W1[i*64+j]
    __shared__ float sW2 [256];  // [j][c] row-major (native layout of W2)
    __shared__ float sB1 [64];
    int tid = threadIdx.x;
    #pragma unroll
    for (int k = tid; k < 256; k += 64) {
        sW1T[(k & 63) * 4 + (k >> 6)] = W1[k];  // transpose on load
        sW2[k] = W2[k];
    }
    sB1[tid] = b1[tid];
    __syncthreads();
    cudaGridDependencySynchronize();     // wait: scatter1 reds landed

    const float4* w1t = (const float4*)sW1T;
    const float4* w2  = (const float4*)sW2;

    int i0 = (blockIdx.x * blockDim.x + tid) * 2;
    if (i0 + 1 < n) {
        float d0 = g_dinv[i0],  d1 = g_dinv[i0 + 1];
        float4 a0 = g_acc1[i0], a1 = g_acc1[i0 + 1];
        a0.x *= d0; a0.y *= d0; a0.z *= d0; a0.w *= d0;
        a1.x *= d1; a1.y *= d1; a1.z *= d1; a1.w *= d1;
        float4 g0 = make_float4(0.f, 0.f, 0.f, 0.f);
        float4 g1 = make_float4(0.f, 0.f, 0.f, 0.f);
        #pragma unroll
        for (int j = 0; j < 64; j++) {
            float4 w = w1t[j];
            float4 u = w2[j];
            float  b = sB1[j];
            float h0 = fmaf(a0.x, w.x, fmaf(a0.y, w.y, fmaf(a0.z, w.z, fmaf(a0.w, w.w, b))));
            float h1 = fmaf(a1.x, w.x, fmaf(a1.y, w.y, fmaf(a1.z, w.z, fmaf(a1.w, w.w, b))));
            h0 = fmaxf(h0, 0.0f);
            h1 = fmaxf(h1, 0.0f);
            g0.x = fmaf(h0, u.x, g0.x); g0.y = fmaf(h0, u.y, g0.y);
            g0.z = fmaf(h0, u.z, g0.z); g0.w = fmaf(h0, u.w, g0.w);
            g1.x = fmaf(h1, u.x, g1.x); g1.y = fmaf(h1, u.y, g1.y);
            g1.z = fmaf(h1, u.z, g1.z); g1.w = fmaf(h1, u.w, g1.w);
        }
        float4 s0 = make_float4(g0.x * d0, g0.y * d0, g0.z * d0, g0.w * d0);
        float4 s1 = make_float4(g1.x * d1, g1.y * d1, g1.z * d1, g1.w * d1);
        g_gs[i0]     = s0;  g_acc2[i0]     = s0;
        g_gs[i0 + 1] = s1;  g_acc2[i0 + 1] = s1;
    } else if (i0 < n) {
        float d = g_dinv[i0];
        float4 a = g_acc1[i0];
        a.x *= d; a.y *= d; a.z *= d; a.w *= d;
        float4 g = make_float4(0.f, 0.f, 0.f, 0.f);
        #pragma unroll
        for (int j = 0; j < 64; j++) {
            float4 w = w1t[j];
            float4 u = w2[j];
            float h = fmaf(a.x, w.x, fmaf(a.y, w.y, fmaf(a.z, w.z, fmaf(a.w, w.w, sB1[j]))));
            h = fmaxf(h, 0.0f);
            g.x = fmaf(h, u.x, g.x); g.y = fmaf(h, u.y, g.y);
            g.z = fmaf(h, u.z, g.z); g.w = fmaf(h, u.w, g.w);
        }
        float4 s = make_float4(g.x * d, g.y * d, g.z * d, g.w * d);
        g_gs[i0] = s;  g_acc2[i0] = s;
    }
    cudaTriggerProgrammaticLaunchCompletion();
}

// out = dinv * acc2 + b2
__global__ void k_final(const float* __restrict__ b2, float4* __restrict__ out, int n) {
    int i = blockIdx.x * blockDim.x + threadIdx.x;
    float bx = b2[0], by = b2[1], bz = b2[2], bw = b2[3];  // independent prologue
    cudaGridDependencySynchronize();     // wait: scatter2 reds landed
    if (i < n) {
        float d = g_dinv[i];
        float4 a = g_acc2[i];
        float4 o;
        o.x = fmaf(d, a.x, bx);
        o.y = fmaf(d, a.y, by);
        o.z = fmaf(d, a.z, bz);
        o.w = fmaf(d, a.w, bw);
        out[i] = o;
    }
    cudaTriggerProgrammaticLaunchCompletion();
}

template <typename... Args>
static inline void launch_pdl(void (*kern)(Args...), int grid, int block,
                              Args... args) {
    cudaLaunchConfig_t cfg = {};
    cfg.gridDim  = dim3(grid, 1, 1);
    cfg.blockDim = dim3(block, 1, 1);
    cfg.dynamicSmemBytes = 0;
    cfg.stream = 0;   // legacy default stream (same as <<<>>>)
    cudaLaunchAttribute attr[1];
    attr[0].id = cudaLaunchAttributeProgrammaticStreamSerialization;
    attr[0].val.programmaticStreamSerializationAllowed = 1;
    cfg.attrs = attr;
    cfg.numAttrs = 1;
    cudaLaunchKernelEx(&cfg, kern, args...);
}

extern "C" void kernel_launch(void* const* d_in, const int* in_sizes, int n_in,
                              void* d_out, int out_size) {
    const float* x  = (const float*)d_in[0];
    const int*   ei = (const int*)  d_in[1];
    const float* W1 = (const float*)d_in[2];
    const float* b1 = (const float*)d_in[3];
    const float* W2 = (const float*)d_in[4];
    const float* b2 = (const float*)d_in[5];

    int n = in_sizes[0] / 4;   // N nodes (S=4)
    int e = in_sizes[1] / 2;   // E edges
    const int* row = ei;
    const int* col = ei + e;

    void *p_xs, *p_acc1, *p_gs, *p_acc2;
    cudaGetSymbolAddress(&p_xs,   g_xs);
    cudaGetSymbolAddress(&p_acc1, g_acc1);
    cudaGetSymbolAddress(&p_gs,   g_gs);
    cudaGetSymbolAddress(&p_acc2, g_acc2);

    const int TB  = 256;
    const int TBM = 64;                          // mlp: 2-warp blocks, balanced waves
    int nb_n  = (n + TB - 1) / TB;
    int nb_e1 = (e + TB - 1) / TB;               // 1 edge/thread
    int nt_m  = (n + 1) / 2;                     // 2 nodes/thread (mlp)
    int nb_m  = (nt_m + TBM - 1) / TBM;          // 782 blocks

    launch_pdl(k_deg_count, nb_e1, TB, col, e);
    launch_pdl(k_node_pre,  nb_n,  TB, (const float4*)x, n);
    launch_pdl(k_scatter,   nb_e1, TB, row, col, (const float4*)p_xs, (float4*)p_acc1, e);
    launch_pdl(k_mlp,       nb_m,  TBM, W1, b1, W2, n);
    launch_pdl(k_scatter,   nb_e1, TB, row, col, (const float4*)p_gs, (float4*)p_acc2, e);
    launch_pdl(k_final,     nb_n,  TB, b2, (float4*)d_out, n);
}